// round 12
// baseline (speedup 1.0000x reference)
#include <cuda_runtime.h>
#include <cuda_fp16.h>
#include <math.h>
#include <stdint.h>

#define Q_CODES   4096
#define E_DIM     256
#define ROWS_TOT  32768

#define BM        64      // rows per CTA (vq pass)  [R12: 128 -> 64 for occ 2]
#define BN        128     // codes per tile
#define KCH       64      // k per chunk
#define NTILES    (Q_CODES / BN)        // 32
#define NCH       (E_DIM / KCH)         // 4
#define NSTEPS    (NTILES * NCH)        // 128

#define M_FLAG    4e-4f   // flag margin  (bound 2*maxerr1 ~ 2e-4, 2x safety)
#define M_COLL    4e-4f   // refine collect margin (bound maxerr1+maxerr3 ~ 1.7e-4)

// ---- vq smem offsets (hi-only B), compacted for 2 CTAs/SM ----
#define XSH_OFF   0                     // 64 x 528B = 33792
#define BST0_OFF  33792                 // 128 codes x 144B = 18432
#define BST1_OFF  52224
#define W2S_OFF   70656                 // 4096 floats = 16384
#define SREDB_OFF 87040                 // 64 u64 = 512
#define SREDS_OFF 87552                 // 64 u32 = 256
#define VQ_SMEM   87808                 // x2 CTAs = 175616 < 227KB

// ---- refine smem offsets ----
#define RXH_OFF   0                     // 32 x 528 = 16896
#define RXL_OFF   16896
#define RB0_OFF   33792                 // hi 18432 + lo 18432
#define RB1_OFF   70656
#define RW2_OFF   107520                // 1024 floats
#define RROW_OFF  111616                // 32 ints
#define RF_SMEM   111744

#define BS_ROW_BYTES 144
#define B_TYPE_BYTES 18432

// device scratch
__device__ __half g_xh[ROWS_TOT * E_DIM];
__device__ __half g_wh[Q_CODES * E_DIM];   // scaled by 1024
__device__ __half g_wl[Q_CODES * E_DIM];   // scaled by 1024
__device__ __half g_xh2[ROWS_TOT * E_DIM]; // compacted flagged rows (hi)
__device__ __half g_xl2[ROWS_TOT * E_DIM]; // compacted flagged rows (lo)
__device__ float  g_x2[ROWS_TOT];
__device__ float  g_w2[Q_CODES];
__device__ float  g_bestD[ROWS_TOT];
__device__ int    g_bestI[ROWS_TOT];
__device__ int    g_flag[ROWS_TOT];
__device__ int    g_flagrows[ROWS_TOT];
__device__ int    g_nflag;
__device__ unsigned long long g_red[ROWS_TOT];

// ---------------------------------------------------------------------------
__device__ __forceinline__ uint32_t smem_u32(const void* p) {
    uint32_t a;
    asm("{ .reg .u64 t; cvta.to.shared.u64 t, %1; cvt.u32.u64 %0, t; }" : "=r"(a) : "l"(p));
    return a;
}
#define CP_ASYNC16(dst, src) \
    asm volatile("cp.async.cg.shared.global [%0], [%1], 16;" :: "r"(dst), "l"(src))
#define CP_COMMIT() asm volatile("cp.async.commit_group;" ::: "memory")
#define CP_WAIT1()  asm volatile("cp.async.wait_group 1;" ::: "memory")
#define CP_WAIT0()  asm volatile("cp.async.wait_group 0;" ::: "memory")

#define LDMATRIX_X4(r0, r1, r2, r3, addr) \
    asm volatile("ldmatrix.sync.aligned.m8n8.x4.shared.b16 {%0,%1,%2,%3}, [%4];" \
                 : "=r"(r0), "=r"(r1), "=r"(r2), "=r"(r3) : "r"(addr))

__device__ __forceinline__ void mma16816(float* c, const uint32_t* a, const uint32_t* b) {
    asm volatile(
        "mma.sync.aligned.m16n8k16.row.col.f32.f16.f16.f32 "
        "{%0,%1,%2,%3}, {%4,%5,%6,%7}, {%8,%9}, {%0,%1,%2,%3};"
        : "+f"(c[0]), "+f"(c[1]), "+f"(c[2]), "+f"(c[3])
        : "r"(a[0]), "r"(a[1]), "r"(a[2]), "r"(a[3]), "r"(b[0]), "r"(b[1]));
}

// exact R0-numerics distance (ascending-k fp32 FMA chain)
__device__ __forceinline__ float exact_dist(const float* __restrict__ x,
                                            const float* __restrict__ w,
                                            int row, int code) {
    const float* xr = x + (size_t)row * E_DIM;
    const float* wr = w + (size_t)code * E_DIM;
    float acc = 0.f;
    #pragma unroll 8
    for (int k = 0; k < E_DIM; ++k) acc = fmaf(__ldg(xr + k), __ldg(wr + k), acc);
    return fmaf(-2.0f, acc, g_x2[row]) + g_w2[code];
}

// ---------------------------------------------------------------------------
// fused split(x, hi only) + x2 : 32 rows per block
// ---------------------------------------------------------------------------
__global__ void splitx_x2_kernel(const float* __restrict__ x) {
    __shared__ float xs[32 * E_DIM];
    const int tid = threadIdx.x;
    const int base = blockIdx.x * 32 * E_DIM;
    #pragma unroll
    for (int it = 0; it < 32; ++it) {
        int i = tid + it * 256;
        xs[i] = x[base + i];
    }
    __syncthreads();
    #pragma unroll
    for (int it = 0; it < 32; ++it) {
        int i = tid + it * 256;
        g_xh[base + i] = __float2half_rn(xs[i]);
    }
    if (tid < 32) {
        const float* r = &xs[tid * E_DIM];
        float s = 0.f;
        for (int k = 0; k < E_DIM; ++k) s = fmaf(r[k], r[k], s);
        g_x2[blockIdx.x * 32 + tid] = s;
    }
}

// ---------------------------------------------------------------------------
// fused split(w, scale 1024) + w2 : warp per code (w2 numerics == R0)
// ---------------------------------------------------------------------------
__global__ void splitw_w2_kernel(const float* __restrict__ w) {
    int code = (blockIdx.x * blockDim.x + threadIdx.x) >> 5;
    int lane = threadIdx.x & 31;
    if (code >= Q_CODES) return;
    const float* row = w + (size_t)code * E_DIM;
    float v[8];
    float s = 0.f;
    #pragma unroll
    for (int j = 0; j < 8; ++j) {
        v[j] = row[lane + 32 * j];
        s = fmaf(v[j], v[j], s);
    }
    #pragma unroll
    for (int off = 16; off; off >>= 1) s += __shfl_down_sync(0xffffffffu, s, off);
    if (lane == 0) g_w2[code] = s;
    #pragma unroll
    for (int j = 0; j < 8; ++j) {
        float sv = v[j] * 1024.0f;                 // exact
        __half h = __float2half_rn(sv);
        g_wh[(size_t)code * E_DIM + lane + 32 * j] = h;
        g_wl[(size_t)code * E_DIM + lane + 32 * j] = __float2half_rn(sv - __half2float(h));
    }
}

__global__ void reset_kernel() { if (threadIdx.x == 0) g_nflag = 0; }

// ---------------------------------------------------------------------------
// vq B chunk (hi only)
// ---------------------------------------------------------------------------
__device__ __forceinline__ void vq_issue_chunk(uint32_t smem_u, int s, int tid) {
    const int t = s >> 2, c = s & 3;
    const uint32_t bst = smem_u + ((s & 1) ? BST1_OFF : BST0_OFF);
    const __half* srcH = g_wh + (size_t)(t * BN) * E_DIM + c * KCH;
    #pragma unroll
    for (int it = 0; it < 4; ++it) {
        int i = tid + it * 256;          // 0..1023
        int row = i >> 3, q = i & 7;
        CP_ASYNC16(bst + (uint32_t)(row * BS_ROW_BYTES + q * 16),
                   (const void*)(srcH + row * E_DIM + q * 8));
    }
}

// ---------------------------------------------------------------------------
// vq pass: SINGLE-pass fp16 mma + best/second-best; BM=64, 2 CTAs/SM
// ---------------------------------------------------------------------------
__global__ __launch_bounds__(256, 2)
void vq_kernel() {
    extern __shared__ __align__(128) char smem[];
    const uint32_t smem_u = smem_u32(smem);
    float* w2s = (float*)(smem + W2S_OFF);
    unsigned long long* sredB = (unsigned long long*)(smem + SREDB_OFF);
    unsigned int*       sredS = (unsigned int*)(smem + SREDS_OFF);

    const int tid  = threadIdx.x;
    const int lane = tid & 31;
    const int wid  = tid >> 5;
    const int wm   = wid >> 2;          // 0..1 -> 32 rows each
    const int wn   = wid & 3;           // 0..3 -> 32 codes each
    const int rowBase = blockIdx.x * BM;

    vq_issue_chunk(smem_u, 0, tid);
    CP_COMMIT();

    {   // resident A (hi only), 64 rows, row stride 528B
        const uint4* gh = (const uint4*)(g_xh + (size_t)rowBase * E_DIM);
        #pragma unroll
        for (int it = 0; it < 8; ++it) {
            int i = tid + it * 256;      // 0..2047
            int r = i >> 5, q = i & 31;
            *(uint4*)(smem + XSH_OFF + r * 528 + q * 16) = gh[r * 32 + q];
        }
    }
    #pragma unroll
    for (int it = 0; it < 16; ++it) w2s[tid + it * 256] = g_w2[tid + it * 256];
    if (tid < BM) { sredB[tid] = 0xFFFFFFFFFFFFFFFFull; sredS[tid] = 0xFFFFFFFFu; }

    float x2r[4];
    #pragma unroll
    for (int mf = 0; mf < 2; ++mf)
        #pragma unroll
        for (int h = 0; h < 2; ++h)
            x2r[mf * 2 + h] = g_x2[rowBase + wm * 32 + mf * 16 + h * 8 + (lane >> 2)];

    float bestD[4], secD[4];
    int   bestI[4];
    #pragma unroll
    for (int i = 0; i < 4; ++i) { bestD[i] = INFINITY; secD[i] = INFINITY; bestI[i] = 0; }

    float acc[2][4][4];

    for (int t = 0; t < NTILES; ++t) {
        #pragma unroll
        for (int mf = 0; mf < 2; ++mf)
            #pragma unroll
            for (int nf = 0; nf < 4; ++nf)
                #pragma unroll
                for (int e = 0; e < 4; ++e) acc[mf][nf][e] = 0.f;

        for (int c = 0; c < NCH; ++c) {
            const int s = t * NCH + c;
            if (s + 1 < NSTEPS) { vq_issue_chunk(smem_u, s + 1, tid); CP_COMMIT(); CP_WAIT1(); }
            else                { CP_WAIT0(); }
            __syncthreads();

            const uint32_t bst = smem_u + ((s & 1) ? BST1_OFF : BST0_OFF);
            const int kglob0 = c * KCH;

            #pragma unroll
            for (int kk = 0; kk < 4; ++kk) {
                const int kg = kglob0 + kk * 16;
                const int kl = kk * 16;
                uint32_t Ah[2][4], Bh[4][2];
                #pragma unroll
                for (int mf = 0; mf < 2; ++mf) {
                    uint32_t off = (uint32_t)((wm * 32 + mf * 16 + (lane & 15)) * 528
                                              + (kg + ((lane >> 4) << 3)) * 2);
                    LDMATRIX_X4(Ah[mf][0], Ah[mf][1], Ah[mf][2], Ah[mf][3], smem_u + XSH_OFF + off);
                }
                #pragma unroll
                for (int p = 0; p < 2; ++p) {
                    uint32_t n = (uint32_t)(wn * 32 + p * 16 + (lane & 7) + ((lane >> 4) << 3));
                    uint32_t off = n * BS_ROW_BYTES + (uint32_t)((kl + (((lane >> 3) & 1) << 3)) * 2);
                    LDMATRIX_X4(Bh[p*2][0], Bh[p*2][1], Bh[p*2+1][0], Bh[p*2+1][1], bst + off);
                }
                #pragma unroll
                for (int mf = 0; mf < 2; ++mf)
                    #pragma unroll
                    for (int nf = 0; nf < 4; ++nf) mma16816(acc[mf][nf], Ah[mf], Bh[nf]);
            }
            __syncthreads();
        }

        const int codeBase = t * BN + wn * 32;
        #pragma unroll
        for (int mf = 0; mf < 2; ++mf)
            #pragma unroll
            for (int h = 0; h < 2; ++h) {
                const int slot = mf * 2 + h;
                float x2v = x2r[slot];
                float d0 = bestD[slot], d1 = secD[slot];
                int   i0 = bestI[slot];
                #pragma unroll
                for (int nf = 0; nf < 4; ++nf)
                    #pragma unroll
                    for (int j = 0; j < 2; ++j) {
                        int code  = codeBase + nf * 8 + (lane & 3) * 2 + j;
                        float dot = acc[mf][nf][h * 2 + j] * 0.0009765625f;
                        float dv  = fmaf(-2.0f, dot, x2v) + w2s[code];
                        if (dv < d0)      { d1 = d0; d0 = dv; i0 = code; }
                        else if (dv < d1) { d1 = dv; }
                    }
                bestD[slot] = d0; secD[slot] = d1; bestI[slot] = i0;
            }
    }

    __syncthreads();
    #pragma unroll
    for (int i = 0; i < 4; ++i) {
        int rowLocal = wm * 32 + (i >> 1) * 16 + (i & 1) * 8 + (lane >> 2);
        unsigned long long pack =
            ((unsigned long long)__float_as_uint(bestD[i]) << 32) | (unsigned)bestI[i];
        atomicMin(&sredB[rowLocal], pack);
    }
    __syncthreads();
    #pragma unroll
    for (int i = 0; i < 4; ++i) {
        int rowLocal = wm * 32 + (i >> 1) * 16 + (i & 1) * 8 + (lane >> 2);
        unsigned winIdx = (unsigned)(sredB[rowLocal] & 0xffffffffull);
        float cand = ((unsigned)bestI[i] == winIdx) ? secD[i] : bestD[i];
        atomicMin(&sredS[rowLocal], __float_as_uint(cand));
    }
    __syncthreads();

    if (tid < BM) {
        unsigned long long bp = sredB[tid];
        float bd = __uint_as_float((unsigned)(bp >> 32));
        float sd = __uint_as_float(sredS[tid]);
        int row = rowBase + tid;
        g_bestI[row] = (int)(bp & 0xffffffffull);
        g_bestD[row] = bd;
        g_flag[row]  = (sd - bd <= M_FLAG) ? 1 : 0;
    }
}

// ---------------------------------------------------------------------------
__global__ void compact_kernel() {
    int r = blockIdx.x * blockDim.x + threadIdx.x;
    if (r >= ROWS_TOT) return;
    if (g_flag[r]) {
        int p = atomicAdd(&g_nflag, 1);
        g_flagrows[p] = r;
        g_red[r] = 0xFFFFFFFFFFFFFFFFull;
    }
}

// copy flagged rows; recompute hi/lo split from fp32 x (identical formula)
__global__ void copyrows_kernel(const float* __restrict__ x) {
    const int nf = g_nflag;
    const int t = threadIdx.x;              // 64 threads, 4 floats each
    for (int p = blockIdx.x; p < nf; p += gridDim.x) {
        int row = g_flagrows[p];
        const float4 v4 = ((const float4*)(x + (size_t)row * E_DIM))[t];
        __half2* dh = (__half2*)(g_xh2 + (size_t)p * E_DIM) + t * 2;
        __half2* dl = (__half2*)(g_xl2 + (size_t)p * E_DIM) + t * 2;
        float f[4] = {v4.x, v4.y, v4.z, v4.w};
        __half h[4], l[4];
        #pragma unroll
        for (int j = 0; j < 4; ++j) {
            h[j] = __float2half_rn(f[j]);
            l[j] = __float2half_rn(f[j] - __half2float(h[j]));
        }
        dh[0] = __halves2half2(h[0], h[1]);
        dh[1] = __halves2half2(h[2], h[3]);
        dl[0] = __halves2half2(l[0], l[1]);
        dl[1] = __halves2half2(l[2], l[3]);
    }
}

// ---------------------------------------------------------------------------
// refine B chunk (hi + lo)
// ---------------------------------------------------------------------------
__device__ __forceinline__ void rf_issue_chunk(uint32_t smem_u, int quarter, int s, int tid) {
    const int t = s >> 2, c = s & 3;
    const int codeBase = quarter * 1024 + t * BN;
    const uint32_t bst = smem_u + ((s & 1) ? RB1_OFF : RB0_OFF);
    const __half* srcH = g_wh + (size_t)codeBase * E_DIM + c * KCH;
    const __half* srcL = g_wl + (size_t)codeBase * E_DIM + c * KCH;
    #pragma unroll
    for (int it = 0; it < 4; ++it) {
        int i = tid + it * 256;
        int row = i >> 3, q = i & 7;
        uint32_t dst = bst + (uint32_t)(row * BS_ROW_BYTES + q * 16);
        CP_ASYNC16(dst, (const void*)(srcH + row * E_DIM + q * 8));
        CP_ASYNC16(dst + B_TYPE_BYTES, (const void*)(srcL + row * E_DIM + q * 8));
    }
}

// ---------------------------------------------------------------------------
// refine: flagged rows, 3-pass fp16 mma; candidates (dv <= bestD+M) -> exact
// ---------------------------------------------------------------------------
__global__ __launch_bounds__(256, 1)
void refine_kernel(const float* __restrict__ x, const float* __restrict__ w) {
    extern __shared__ __align__(128) char smem[];
    const uint32_t smem_u = smem_u32(smem);
    float* w2q  = (float*)(smem + RW2_OFF);
    int*   srow = (int*)(smem + RROW_OFF);

    const int tid  = threadIdx.x;
    const int lane = tid & 31;
    const int wid  = tid >> 5;
    const int wm   = wid >> 2;          // 0..1 -> 16 rows each
    const int wn   = wid & 3;

    const int nflag  = g_nflag;
    const int nItems = ((nflag + 31) >> 5) * 4;

    for (int item = blockIdx.x; item < nItems; item += gridDim.x) {
        const int grp = item >> 2, quarter = item & 3;
        __syncthreads();                 // smem reuse across items

        rf_issue_chunk(smem_u, quarter, 0, tid);
        CP_COMMIT();

        #pragma unroll
        for (int it = 0; it < 4; ++it) {
            int i = tid + it * 256;      // 0..1023
            int r = i >> 5, q = i & 31;
            int p = grp * 32 + r; if (p >= nflag) p = nflag - 1;
            *(uint4*)(smem + RXH_OFF + r * 528 + q * 16) =
                ((const uint4*)(g_xh2 + (size_t)p * E_DIM))[q];
            *(uint4*)(smem + RXL_OFF + r * 528 + q * 16) =
                ((const uint4*)(g_xl2 + (size_t)p * E_DIM))[q];
        }
        #pragma unroll
        for (int it = 0; it < 4; ++it)
            w2q[tid + it * 256] = g_w2[quarter * 1024 + tid + it * 256];
        if (tid < 32) {
            int p = grp * 32 + tid; if (p >= nflag) p = nflag - 1;
            srow[tid] = g_flagrows[p];
        }
        __syncthreads();

        int   rid[2]; float x2v[2], thr[2];
        #pragma unroll
        for (int h = 0; h < 2; ++h) {
            int rl = wm * 16 + h * 8 + (lane >> 2);
            rid[h] = srow[rl];
            x2v[h] = g_x2[rid[h]];
            thr[h] = g_bestD[rid[h]] + M_COLL;
        }

        for (int t = 0; t < 8; ++t) {
            float acc[4][4];
            #pragma unroll
            for (int nf = 0; nf < 4; ++nf)
                #pragma unroll
                for (int e = 0; e < 4; ++e) acc[nf][e] = 0.f;

            for (int c = 0; c < 4; ++c) {
                const int s = t * 4 + c;
                if (s + 1 < 32) { rf_issue_chunk(smem_u, quarter, s + 1, tid); CP_COMMIT(); CP_WAIT1(); }
                else            { CP_WAIT0(); }
                __syncthreads();

                const uint32_t bst = smem_u + ((s & 1) ? RB1_OFF : RB0_OFF);
                const int kglob0 = c * KCH;

                #pragma unroll
                for (int kk = 0; kk < 4; ++kk) {
                    const int kg = kglob0 + kk * 16;
                    const int kl = kk * 16;
                    uint32_t Ah[4], Al[4], Bh[4][2], Bl[4][2];
                    {
                        uint32_t off = (uint32_t)((wm * 16 + (lane & 15)) * 528
                                                  + (kg + ((lane >> 4) << 3)) * 2);
                        LDMATRIX_X4(Ah[0], Ah[1], Ah[2], Ah[3], smem_u + RXH_OFF + off);
                        LDMATRIX_X4(Al[0], Al[1], Al[2], Al[3], smem_u + RXL_OFF + off);
                    }
                    #pragma unroll
                    for (int p = 0; p < 2; ++p) {
                        uint32_t n = (uint32_t)(wn * 32 + p * 16 + (lane & 7) + ((lane >> 4) << 3));
                        uint32_t off = n * BS_ROW_BYTES + (uint32_t)((kl + (((lane >> 3) & 1) << 3)) * 2);
                        LDMATRIX_X4(Bh[p*2][0], Bh[p*2][1], Bh[p*2+1][0], Bh[p*2+1][1], bst + off);
                        LDMATRIX_X4(Bl[p*2][0], Bl[p*2][1], Bl[p*2+1][0], Bl[p*2+1][1],
                                    bst + B_TYPE_BYTES + off);
                    }
                    #pragma unroll
                    for (int nf = 0; nf < 4; ++nf) mma16816(acc[nf], Ah, Bh[nf]);
                    #pragma unroll
                    for (int nf = 0; nf < 4; ++nf) mma16816(acc[nf], Al, Bh[nf]);
                    #pragma unroll
                    for (int nf = 0; nf < 4; ++nf) mma16816(acc[nf], Ah, Bl[nf]);
                }
                __syncthreads();
            }

            const int codeBase = quarter * 1024 + t * BN + wn * 32;
            #pragma unroll
            for (int h = 0; h < 2; ++h)
                #pragma unroll
                for (int nf = 0; nf < 4; ++nf)
                    #pragma unroll
                    for (int j = 0; j < 2; ++j) {
                        int code  = codeBase + nf * 8 + (lane & 3) * 2 + j;
                        float dot = acc[nf][h * 2 + j] * 0.0009765625f;
                        float dv  = fmaf(-2.0f, dot, x2v[h]) + w2q[t * BN + wn * 32 + nf * 8 + (lane & 3) * 2 + j];
                        if (dv <= thr[h]) {
                            float de = exact_dist(x, w, rid[h], code);
                            unsigned long long pack =
                                ((unsigned long long)__float_as_uint(de) << 32) | (unsigned)code;
                            atomicMin(&g_red[rid[h]], pack);
                        }
                    }
        }
    }
}

// ---------------------------------------------------------------------------
// gather: 4 rows per 256-thread block
// ---------------------------------------------------------------------------
__global__ void gather_kernel(const float* __restrict__ w, float* __restrict__ out,
                              float* __restrict__ out_idx_f) {
    const int t   = threadIdx.x;
    const int row = blockIdx.x * 4 + (t >> 6);
    const int q   = t & 63;
    int idx = g_flag[row] ? (int)(g_red[row] & 0xffffffffull) : g_bestI[row];
    ((float4*)(out + (size_t)row * E_DIM))[q] =
        ((const float4*)(w + (size_t)idx * E_DIM))[q];
    if (q == 0) out_idx_f[row] = (float)idx;
}

// ---------------------------------------------------------------------------
extern "C" void kernel_launch(void* const* d_in, const int* in_sizes, int n_in,
                              void* d_out, int out_size) {
    const float* x = (const float*)d_in[0];
    const float* w = (const float*)d_in[1];
    int rows = in_sizes[0] / E_DIM;        // 32768

    float* out     = (float*)d_out;
    float* out_idx = out + (size_t)rows * E_DIM;

    cudaFuncSetAttribute(vq_kernel,
                         cudaFuncAttributeMaxDynamicSharedMemorySize, VQ_SMEM);
    cudaFuncSetAttribute(refine_kernel,
                         cudaFuncAttributeMaxDynamicSharedMemorySize, RF_SMEM);

    splitx_x2_kernel<<<rows / 32, 256>>>(x);                  // 1
    splitw_w2_kernel<<<Q_CODES / 8, 256>>>(w);                // 2
    reset_kernel<<<1, 32>>>();                                // 3
    vq_kernel<<<rows / BM, 256, VQ_SMEM>>>();                 // 4  <- ncu target
    compact_kernel<<<(ROWS_TOT + 255) / 256, 256>>>();        // 5
    copyrows_kernel<<<1024, 64>>>(x);                         // 6
    refine_kernel<<<444, 256, RF_SMEM>>>(x, w);               // 7
    gather_kernel<<<rows / 4, 256>>>(w, out, out_idx);        // 8
}

// round 13
// speedup vs baseline: 1.0614x; 1.0614x over previous
#include <cuda_runtime.h>
#include <cuda_fp16.h>
#include <math.h>
#include <stdint.h>

#define Q_CODES   4096
#define E_DIM     256
#define ROWS_TOT  32768

#define BM        128     // rows per CTA (vq pass)  [R13: back to 128]
#define BN        128     // codes per tile
#define NTILES    (Q_CODES / BN)        // 32

#define M_FLAG    4e-4f   // flag margin  (bound 2*maxerr1 ~ 2e-4, 2x safety)
#define M_COLL    4e-4f   // refine collect margin (bound maxerr1+maxerr3 ~ 1.7e-4)

// ---- vq smem offsets: A + 2 full B-tile stages (528B row stride) ----
#define XSH_OFF   0                     // 128 x 528B = 67584
#define BST0_OFF  67584                 // 128 codes x 528B = 67584
#define BST1_OFF  135168
#define W2S_OFF   202752                // 4096 floats = 16384
#define SREDB_OFF 219136                // 128 u64 = 1024
#define SREDS_OFF 220160                // 128 u32 = 512
#define VQ_SMEM   220672                // < 227KB opt-in

// ---- refine smem offsets (unchanged, proven) ----
#define RXH_OFF   0                     // 32 x 528 = 16896
#define RXL_OFF   16896
#define RB0_OFF   33792                 // hi 18432 + lo 18432
#define RB1_OFF   70656
#define RW2_OFF   107520                // 1024 floats
#define RROW_OFF  111616                // 32 ints
#define RF_SMEM   111744

#define BS_ROW_BYTES 144                // refine B row stride
#define B_TYPE_BYTES 18432

// device scratch
__device__ __half g_xh[ROWS_TOT * E_DIM];
__device__ __half g_wh[Q_CODES * E_DIM];   // scaled by 1024
__device__ __half g_wl[Q_CODES * E_DIM];   // scaled by 1024
__device__ __half g_xh2[ROWS_TOT * E_DIM]; // compacted flagged rows (hi)
__device__ __half g_xl2[ROWS_TOT * E_DIM]; // compacted flagged rows (lo)
__device__ float  g_x2[ROWS_TOT];
__device__ float  g_w2[Q_CODES];
__device__ float  g_bestD[ROWS_TOT];
__device__ int    g_bestI[ROWS_TOT];
__device__ int    g_flag[ROWS_TOT];
__device__ int    g_flagrows[ROWS_TOT];
__device__ int    g_nflag;
__device__ unsigned long long g_red[ROWS_TOT];

// ---------------------------------------------------------------------------
__device__ __forceinline__ uint32_t smem_u32(const void* p) {
    uint32_t a;
    asm("{ .reg .u64 t; cvta.to.shared.u64 t, %1; cvt.u32.u64 %0, t; }" : "=r"(a) : "l"(p));
    return a;
}
#define CP_ASYNC16(dst, src) \
    asm volatile("cp.async.cg.shared.global [%0], [%1], 16;" :: "r"(dst), "l"(src))
#define CP_COMMIT() asm volatile("cp.async.commit_group;" ::: "memory")
#define CP_WAIT1()  asm volatile("cp.async.wait_group 1;" ::: "memory")
#define CP_WAIT0()  asm volatile("cp.async.wait_group 0;" ::: "memory")

#define LDMATRIX_X4(r0, r1, r2, r3, addr) \
    asm volatile("ldmatrix.sync.aligned.m8n8.x4.shared.b16 {%0,%1,%2,%3}, [%4];" \
                 : "=r"(r0), "=r"(r1), "=r"(r2), "=r"(r3) : "r"(addr))

__device__ __forceinline__ void mma16816(float* c, const uint32_t* a, const uint32_t* b) {
    asm volatile(
        "mma.sync.aligned.m16n8k16.row.col.f32.f16.f16.f32 "
        "{%0,%1,%2,%3}, {%4,%5,%6,%7}, {%8,%9}, {%0,%1,%2,%3};"
        : "+f"(c[0]), "+f"(c[1]), "+f"(c[2]), "+f"(c[3])
        : "r"(a[0]), "r"(a[1]), "r"(a[2]), "r"(a[3]), "r"(b[0]), "r"(b[1]));
}

// exact R0-numerics distance (ascending-k fp32 FMA chain)
__device__ __forceinline__ float exact_dist(const float* __restrict__ x,
                                            const float* __restrict__ w,
                                            int row, int code) {
    const float* xr = x + (size_t)row * E_DIM;
    const float* wr = w + (size_t)code * E_DIM;
    float acc = 0.f;
    #pragma unroll 8
    for (int k = 0; k < E_DIM; ++k) acc = fmaf(__ldg(xr + k), __ldg(wr + k), acc);
    return fmaf(-2.0f, acc, g_x2[row]) + g_w2[code];
}

// ---------------------------------------------------------------------------
// fused split(x, hi only) + x2 : 32 rows per block
// ---------------------------------------------------------------------------
__global__ void splitx_x2_kernel(const float* __restrict__ x) {
    __shared__ float xs[32 * E_DIM];
    const int tid = threadIdx.x;
    const int base = blockIdx.x * 32 * E_DIM;
    #pragma unroll
    for (int it = 0; it < 32; ++it) {
        int i = tid + it * 256;
        xs[i] = x[base + i];
    }
    __syncthreads();
    #pragma unroll
    for (int it = 0; it < 32; ++it) {
        int i = tid + it * 256;
        g_xh[base + i] = __float2half_rn(xs[i]);
    }
    if (tid < 32) {
        const float* r = &xs[tid * E_DIM];
        float s = 0.f;
        for (int k = 0; k < E_DIM; ++k) s = fmaf(r[k], r[k], s);
        g_x2[blockIdx.x * 32 + tid] = s;
    }
}

// ---------------------------------------------------------------------------
// fused split(w, scale 1024) + w2 : warp per code (w2 numerics == R0)
// ---------------------------------------------------------------------------
__global__ void splitw_w2_kernel(const float* __restrict__ w) {
    int code = (blockIdx.x * blockDim.x + threadIdx.x) >> 5;
    int lane = threadIdx.x & 31;
    if (code >= Q_CODES) return;
    const float* row = w + (size_t)code * E_DIM;
    float v[8];
    float s = 0.f;
    #pragma unroll
    for (int j = 0; j < 8; ++j) {
        v[j] = row[lane + 32 * j];
        s = fmaf(v[j], v[j], s);
    }
    #pragma unroll
    for (int off = 16; off; off >>= 1) s += __shfl_down_sync(0xffffffffu, s, off);
    if (lane == 0) g_w2[code] = s;
    #pragma unroll
    for (int j = 0; j < 8; ++j) {
        float sv = v[j] * 1024.0f;                 // exact
        __half h = __float2half_rn(sv);
        g_wh[(size_t)code * E_DIM + lane + 32 * j] = h;
        g_wl[(size_t)code * E_DIM + lane + 32 * j] = __float2half_rn(sv - __half2float(h));
    }
}

__global__ void reset_kernel() { if (threadIdx.x == 0) g_nflag = 0; }

// ---------------------------------------------------------------------------
// vq B tile (hi only): full 128 codes x 256 k per stage
// ---------------------------------------------------------------------------
__device__ __forceinline__ void vq_issue_tile(uint32_t smem_u, int t, int tid) {
    const uint32_t bst = smem_u + ((t & 1) ? BST1_OFF : BST0_OFF);
    const __half* srcH = g_wh + (size_t)(t * BN) * E_DIM;
    #pragma unroll
    for (int it = 0; it < 16; ++it) {
        int i = tid + it * 256;          // 0..4095
        int row = i >> 5, q = i & 31;    // 32 x 16B units per code row
        CP_ASYNC16(bst + (uint32_t)(row * 528 + q * 16),
                   (const void*)(srcH + row * E_DIM + q * 8));
    }
}

// ---------------------------------------------------------------------------
// vq pass: single-pass fp16 mma, full-tile staging, ONE barrier per tile
// ---------------------------------------------------------------------------
__global__ __launch_bounds__(256, 1)
void vq_kernel() {
    extern __shared__ __align__(128) char smem[];
    const uint32_t smem_u = smem_u32(smem);
    float* w2s = (float*)(smem + W2S_OFF);
    unsigned long long* sredB = (unsigned long long*)(smem + SREDB_OFF);
    unsigned int*       sredS = (unsigned int*)(smem + SREDS_OFF);

    const int tid  = threadIdx.x;
    const int lane = tid & 31;
    const int wid  = tid >> 5;
    const int wm   = wid >> 2;          // 0..1 -> 64 rows each
    const int wn   = wid & 3;           // 0..3 -> 32 codes each
    const int rowBase = blockIdx.x * BM;

    vq_issue_tile(smem_u, 0, tid);
    CP_COMMIT();

    {   // resident A (hi only), 128 rows, row stride 528B
        const uint4* gh = (const uint4*)(g_xh + (size_t)rowBase * E_DIM);
        #pragma unroll
        for (int it = 0; it < 16; ++it) {
            int i = tid + it * 256;      // 0..4095
            int r = i >> 5, q = i & 31;
            *(uint4*)(smem + XSH_OFF + r * 528 + q * 16) = gh[r * 32 + q];
        }
    }
    #pragma unroll
    for (int it = 0; it < 16; ++it) w2s[tid + it * 256] = g_w2[tid + it * 256];
    if (tid < BM) { sredB[tid] = 0xFFFFFFFFFFFFFFFFull; sredS[tid] = 0xFFFFFFFFu; }

    float x2r[8];
    #pragma unroll
    for (int mf = 0; mf < 4; ++mf)
        #pragma unroll
        for (int h = 0; h < 2; ++h)
            x2r[mf * 2 + h] = g_x2[rowBase + wm * 64 + mf * 16 + h * 8 + (lane >> 2)];

    float bestD[8], secD[8];
    int   bestI[8];
    #pragma unroll
    for (int i = 0; i < 8; ++i) { bestD[i] = INFINITY; secD[i] = INFINITY; bestI[i] = 0; }

    float acc[4][4][4];

    for (int t = 0; t < NTILES; ++t) {
        CP_WAIT0();                      // tile t landed (only group in flight)
        __syncthreads();                 // all threads past tile t-1 reads; data visible
        if (t + 1 < NTILES) { vq_issue_tile(smem_u, t + 1, tid); CP_COMMIT(); }

        const uint32_t bst = smem_u + ((t & 1) ? BST1_OFF : BST0_OFF);

        #pragma unroll
        for (int mf = 0; mf < 4; ++mf)
            #pragma unroll
            for (int nf = 0; nf < 4; ++nf)
                #pragma unroll
                for (int e = 0; e < 4; ++e) acc[mf][nf][e] = 0.f;

        #pragma unroll 4
        for (int kk = 0; kk < 16; ++kk) {
            const int kg = kk * 16;
            uint32_t Ah[4][4], Bh[4][2];
            #pragma unroll
            for (int mf = 0; mf < 4; ++mf) {
                uint32_t off = (uint32_t)((wm * 64 + mf * 16 + (lane & 15)) * 528
                                          + (kg + ((lane >> 4) << 3)) * 2);
                LDMATRIX_X4(Ah[mf][0], Ah[mf][1], Ah[mf][2], Ah[mf][3], smem_u + XSH_OFF + off);
            }
            #pragma unroll
            for (int p = 0; p < 2; ++p) {
                uint32_t n = (uint32_t)(wn * 32 + p * 16 + (lane & 7) + ((lane >> 4) << 3));
                uint32_t off = n * 528 + (uint32_t)((kg + (((lane >> 3) & 1) << 3)) * 2);
                LDMATRIX_X4(Bh[p*2][0], Bh[p*2][1], Bh[p*2+1][0], Bh[p*2+1][1], bst + off);
            }
            #pragma unroll
            for (int mf = 0; mf < 4; ++mf)
                #pragma unroll
                for (int nf = 0; nf < 4; ++nf) mma16816(acc[mf][nf], Ah[mf], Bh[nf]);
        }

        // epilogue tile t (registers + read-only w2s; no barrier needed)
        const int codeBase = t * BN + wn * 32;
        #pragma unroll
        for (int mf = 0; mf < 4; ++mf)
            #pragma unroll
            for (int h = 0; h < 2; ++h) {
                const int slot = mf * 2 + h;
                float x2v = x2r[slot];
                float d0 = bestD[slot], d1 = secD[slot];
                int   i0 = bestI[slot];
                #pragma unroll
                for (int nf = 0; nf < 4; ++nf)
                    #pragma unroll
                    for (int j = 0; j < 2; ++j) {
                        int code  = codeBase + nf * 8 + (lane & 3) * 2 + j;
                        float dot = acc[mf][nf][h * 2 + j] * 0.0009765625f;
                        float dv  = fmaf(-2.0f, dot, x2v) + w2s[code];
                        if (dv < d0)      { d1 = d0; d0 = dv; i0 = code; }
                        else if (dv < d1) { d1 = dv; }
                    }
                bestD[slot] = d0; secD[slot] = d1; bestI[slot] = i0;
            }
    }

    __syncthreads();
    #pragma unroll
    for (int i = 0; i < 8; ++i) {
        int rowLocal = wm * 64 + (i >> 1) * 16 + (i & 1) * 8 + (lane >> 2);
        unsigned long long pack =
            ((unsigned long long)__float_as_uint(bestD[i]) << 32) | (unsigned)bestI[i];
        atomicMin(&sredB[rowLocal], pack);
    }
    __syncthreads();
    #pragma unroll
    for (int i = 0; i < 8; ++i) {
        int rowLocal = wm * 64 + (i >> 1) * 16 + (i & 1) * 8 + (lane >> 2);
        unsigned winIdx = (unsigned)(sredB[rowLocal] & 0xffffffffull);
        float cand = ((unsigned)bestI[i] == winIdx) ? secD[i] : bestD[i];
        atomicMin(&sredS[rowLocal], __float_as_uint(cand));
    }
    __syncthreads();

    if (tid < BM) {
        unsigned long long bp = sredB[tid];
        float bd = __uint_as_float((unsigned)(bp >> 32));
        float sd = __uint_as_float(sredS[tid]);
        int row = rowBase + tid;
        g_bestI[row] = (int)(bp & 0xffffffffull);
        g_bestD[row] = bd;
        g_flag[row]  = (sd - bd <= M_FLAG) ? 1 : 0;
    }
}

// ---------------------------------------------------------------------------
// fused compact + row copy: flagging thread claims slot and writes the
// compacted hi/lo split (identical formula to the proven copyrows path)
// ---------------------------------------------------------------------------
__global__ void compactcopy_kernel(const float* __restrict__ x) {
    int r = blockIdx.x * blockDim.x + threadIdx.x;
    if (r >= ROWS_TOT) return;
    if (!g_flag[r]) return;
    int p = atomicAdd(&g_nflag, 1);
    g_flagrows[p] = r;
    g_red[r] = 0xFFFFFFFFFFFFFFFFull;

    const float4* src = (const float4*)(x + (size_t)r * E_DIM);
    __half2* dh = (__half2*)(g_xh2 + (size_t)p * E_DIM);
    __half2* dl = (__half2*)(g_xl2 + (size_t)p * E_DIM);
    #pragma unroll 4
    for (int q = 0; q < 64; ++q) {
        float4 v4 = __ldg(src + q);
        float f[4] = {v4.x, v4.y, v4.z, v4.w};
        __half h[4], l[4];
        #pragma unroll
        for (int j = 0; j < 4; ++j) {
            h[j] = __float2half_rn(f[j]);
            l[j] = __float2half_rn(f[j] - __half2float(h[j]));
        }
        dh[q * 2]     = __halves2half2(h[0], h[1]);
        dh[q * 2 + 1] = __halves2half2(h[2], h[3]);
        dl[q * 2]     = __halves2half2(l[0], l[1]);
        dl[q * 2 + 1] = __halves2half2(l[2], l[3]);
    }
}

// ---------------------------------------------------------------------------
// refine B chunk (hi + lo)  [unchanged, proven]
// ---------------------------------------------------------------------------
__device__ __forceinline__ void rf_issue_chunk(uint32_t smem_u, int quarter, int s, int tid) {
    const int t = s >> 2, c = s & 3;
    const int codeBase = quarter * 1024 + t * BN;
    const uint32_t bst = smem_u + ((s & 1) ? RB1_OFF : RB0_OFF);
    const __half* srcH = g_wh + (size_t)codeBase * E_DIM + c * 64;
    const __half* srcL = g_wl + (size_t)codeBase * E_DIM + c * 64;
    #pragma unroll
    for (int it = 0; it < 4; ++it) {
        int i = tid + it * 256;
        int row = i >> 3, q = i & 7;
        uint32_t dst = bst + (uint32_t)(row * BS_ROW_BYTES + q * 16);
        CP_ASYNC16(dst, (const void*)(srcH + row * E_DIM + q * 8));
        CP_ASYNC16(dst + B_TYPE_BYTES, (const void*)(srcL + row * E_DIM + q * 8));
    }
}

// ---------------------------------------------------------------------------
// refine: flagged rows, 3-pass fp16 mma; candidates (dv <= bestD+M) -> exact
// ---------------------------------------------------------------------------
__global__ __launch_bounds__(256, 1)
void refine_kernel(const float* __restrict__ x, const float* __restrict__ w) {
    extern __shared__ __align__(128) char smem[];
    const uint32_t smem_u = smem_u32(smem);
    float* w2q  = (float*)(smem + RW2_OFF);
    int*   srow = (int*)(smem + RROW_OFF);

    const int tid  = threadIdx.x;
    const int lane = tid & 31;
    const int wid  = tid >> 5;
    const int wm   = wid >> 2;          // 0..1 -> 16 rows each
    const int wn   = wid & 3;

    const int nflag  = g_nflag;
    const int nItems = ((nflag + 31) >> 5) * 4;

    for (int item = blockIdx.x; item < nItems; item += gridDim.x) {
        const int grp = item >> 2, quarter = item & 3;
        __syncthreads();                 // smem reuse across items

        rf_issue_chunk(smem_u, quarter, 0, tid);
        CP_COMMIT();

        #pragma unroll
        for (int it = 0; it < 4; ++it) {
            int i = tid + it * 256;      // 0..1023
            int r = i >> 5, q = i & 31;
            int p = grp * 32 + r; if (p >= nflag) p = nflag - 1;
            *(uint4*)(smem + RXH_OFF + r * 528 + q * 16) =
                ((const uint4*)(g_xh2 + (size_t)p * E_DIM))[q];
            *(uint4*)(smem + RXL_OFF + r * 528 + q * 16) =
                ((const uint4*)(g_xl2 + (size_t)p * E_DIM))[q];
        }
        #pragma unroll
        for (int it = 0; it < 4; ++it)
            w2q[tid + it * 256] = g_w2[quarter * 1024 + tid + it * 256];
        if (tid < 32) {
            int p = grp * 32 + tid; if (p >= nflag) p = nflag - 1;
            srow[tid] = g_flagrows[p];
        }
        __syncthreads();

        int   rid[2]; float x2v[2], thr[2];
        #pragma unroll
        for (int h = 0; h < 2; ++h) {
            int rl = wm * 16 + h * 8 + (lane >> 2);
            rid[h] = srow[rl];
            x2v[h] = g_x2[rid[h]];
            thr[h] = g_bestD[rid[h]] + M_COLL;
        }

        for (int t = 0; t < 8; ++t) {
            float acc[4][4];
            #pragma unroll
            for (int nf = 0; nf < 4; ++nf)
                #pragma unroll
                for (int e = 0; e < 4; ++e) acc[nf][e] = 0.f;

            for (int c = 0; c < 4; ++c) {
                const int s = t * 4 + c;
                if (s + 1 < 32) { rf_issue_chunk(smem_u, quarter, s + 1, tid); CP_COMMIT(); CP_WAIT1(); }
                else            { CP_WAIT0(); }
                __syncthreads();

                const uint32_t bst = smem_u + ((s & 1) ? RB1_OFF : RB0_OFF);

                #pragma unroll
                for (int kk = 0; kk < 4; ++kk) {
                    const int kg = c * 64 + kk * 16;
                    const int kl = kk * 16;
                    uint32_t Ah[4], Al[4], Bh[4][2], Bl[4][2];
                    {
                        uint32_t off = (uint32_t)((wm * 16 + (lane & 15)) * 528
                                                  + (kg + ((lane >> 4) << 3)) * 2);
                        LDMATRIX_X4(Ah[0], Ah[1], Ah[2], Ah[3], smem_u + RXH_OFF + off);
                        LDMATRIX_X4(Al[0], Al[1], Al[2], Al[3], smem_u + RXL_OFF + off);
                    }
                    #pragma unroll
                    for (int p = 0; p < 2; ++p) {
                        uint32_t n = (uint32_t)(wn * 32 + p * 16 + (lane & 7) + ((lane >> 4) << 3));
                        uint32_t off = n * BS_ROW_BYTES + (uint32_t)((kl + (((lane >> 3) & 1) << 3)) * 2);
                        LDMATRIX_X4(Bh[p*2][0], Bh[p*2][1], Bh[p*2+1][0], Bh[p*2+1][1], bst + off);
                        LDMATRIX_X4(Bl[p*2][0], Bl[p*2][1], Bl[p*2+1][0], Bl[p*2+1][1],
                                    bst + B_TYPE_BYTES + off);
                    }
                    #pragma unroll
                    for (int nf = 0; nf < 4; ++nf) mma16816(acc[nf], Ah, Bh[nf]);
                    #pragma unroll
                    for (int nf = 0; nf < 4; ++nf) mma16816(acc[nf], Al, Bh[nf]);
                    #pragma unroll
                    for (int nf = 0; nf < 4; ++nf) mma16816(acc[nf], Ah, Bl[nf]);
                }
                __syncthreads();
            }

            const int codeBase = quarter * 1024 + t * BN + wn * 32;
            #pragma unroll
            for (int h = 0; h < 2; ++h)
                #pragma unroll
                for (int nf = 0; nf < 4; ++nf)
                    #pragma unroll
                    for (int j = 0; j < 2; ++j) {
                        int code  = codeBase + nf * 8 + (lane & 3) * 2 + j;
                        float dot = acc[nf][h * 2 + j] * 0.0009765625f;
                        float dv  = fmaf(-2.0f, dot, x2v[h]) + w2q[t * BN + wn * 32 + nf * 8 + (lane & 3) * 2 + j];
                        if (dv <= thr[h]) {
                            float de = exact_dist(x, w, rid[h], code);
                            unsigned long long pack =
                                ((unsigned long long)__float_as_uint(de) << 32) | (unsigned)code;
                            atomicMin(&g_red[rid[h]], pack);
                        }
                    }
        }
    }
}

// ---------------------------------------------------------------------------
// gather: 4 rows per 256-thread block
// ---------------------------------------------------------------------------
__global__ void gather_kernel(const float* __restrict__ w, float* __restrict__ out,
                              float* __restrict__ out_idx_f) {
    const int t   = threadIdx.x;
    const int row = blockIdx.x * 4 + (t >> 6);
    const int q   = t & 63;
    int idx = g_flag[row] ? (int)(g_red[row] & 0xffffffffull) : g_bestI[row];
    ((float4*)(out + (size_t)row * E_DIM))[q] =
        ((const float4*)(w + (size_t)idx * E_DIM))[q];
    if (q == 0) out_idx_f[row] = (float)idx;
}

// ---------------------------------------------------------------------------
extern "C" void kernel_launch(void* const* d_in, const int* in_sizes, int n_in,
                              void* d_out, int out_size) {
    const float* x = (const float*)d_in[0];
    const float* w = (const float*)d_in[1];
    int rows = in_sizes[0] / E_DIM;        // 32768

    float* out     = (float*)d_out;
    float* out_idx = out + (size_t)rows * E_DIM;

    cudaFuncSetAttribute(vq_kernel,
                         cudaFuncAttributeMaxDynamicSharedMemorySize, VQ_SMEM);
    cudaFuncSetAttribute(refine_kernel,
                         cudaFuncAttributeMaxDynamicSharedMemorySize, RF_SMEM);

    splitx_x2_kernel<<<rows / 32, 256>>>(x);                  // 1
    splitw_w2_kernel<<<Q_CODES / 8, 256>>>(w);                // 2
    reset_kernel<<<1, 32>>>();                                // 3
    vq_kernel<<<rows / BM, 256, VQ_SMEM>>>();                 // 4  <- ncu target
    compactcopy_kernel<<<(ROWS_TOT + 255) / 256, 256>>>(x);   // 5
    refine_kernel<<<296, 256, RF_SMEM>>>(x, w);               // 6
    gather_kernel<<<rows / 4, 256>>>(w, out, out_idx);        // 7
}

// round 14
// speedup vs baseline: 1.1688x; 1.1012x over previous
#include <cuda_runtime.h>
#include <cuda_fp16.h>
#include <math.h>
#include <stdint.h>

#define Q_CODES   4096
#define E_DIM     256
#define ROWS_TOT  32768

#define BM        128     // rows per CTA (vq pass)
#define BN        128     // codes per tile
#define NTILES    (Q_CODES / BN)        // 32

#define M_FLAG    4e-4f   // flag margin  (bound 2*maxerr1 ~ 2e-4, 2x safety)
#define M_COLL    4e-4f   // refine collect margin (bound maxerr1+maxerr3 ~ 1.7e-4)

// ---- vq smem offsets: A + 2 full B-tile stages (528B row stride) ----
#define XSH_OFF   0                     // 128 x 528B = 67584
#define BST0_OFF  67584                 // 128 codes x 528B = 67584
#define BST1_OFF  135168
#define W2S_OFF   202752                // 4096 floats = 16384
#define SREDB_OFF 219136                // 128 u64 = 1024
#define SREDS_OFF 220160                // 128 u32 = 512
#define VQ_SMEM   220672                // < 227KB opt-in

// ---- refine smem offsets (unchanged, proven) ----
#define RXH_OFF   0                     // 32 x 528 = 16896
#define RXL_OFF   16896
#define RB0_OFF   33792                 // hi 18432 + lo 18432
#define RB1_OFF   70656
#define RW2_OFF   107520                // 1024 floats
#define RROW_OFF  111616                // 32 ints
#define RF_SMEM   111744

#define BS_ROW_BYTES 144                // refine B row stride
#define B_TYPE_BYTES 18432

// device scratch
__device__ __half g_wh[Q_CODES * E_DIM];   // scaled by 1024
__device__ __half g_wl[Q_CODES * E_DIM];   // scaled by 1024
__device__ __half g_xh2[ROWS_TOT * E_DIM]; // compacted flagged rows (hi)
__device__ __half g_xl2[ROWS_TOT * E_DIM]; // compacted flagged rows (lo)
__device__ float  g_x2[ROWS_TOT];
__device__ float  g_w2[Q_CODES];
__device__ float  g_bestD[ROWS_TOT];
__device__ int    g_bestI[ROWS_TOT];
__device__ int    g_flag[ROWS_TOT];
__device__ int    g_flagrows[ROWS_TOT];
__device__ int    g_nflag;
__device__ unsigned long long g_red[ROWS_TOT];

// ---------------------------------------------------------------------------
__device__ __forceinline__ uint32_t smem_u32(const void* p) {
    uint32_t a;
    asm("{ .reg .u64 t; cvta.to.shared.u64 t, %1; cvt.u32.u64 %0, t; }" : "=r"(a) : "l"(p));
    return a;
}
#define CP_ASYNC16(dst, src) \
    asm volatile("cp.async.cg.shared.global [%0], [%1], 16;" :: "r"(dst), "l"(src))
#define CP_COMMIT() asm volatile("cp.async.commit_group;" ::: "memory")
#define CP_WAIT1()  asm volatile("cp.async.wait_group 1;" ::: "memory")
#define CP_WAIT0()  asm volatile("cp.async.wait_group 0;" ::: "memory")

#define LDMATRIX_X4(r0, r1, r2, r3, addr) \
    asm volatile("ldmatrix.sync.aligned.m8n8.x4.shared.b16 {%0,%1,%2,%3}, [%4];" \
                 : "=r"(r0), "=r"(r1), "=r"(r2), "=r"(r3) : "r"(addr))

__device__ __forceinline__ void mma16816(float* c, const uint32_t* a, const uint32_t* b) {
    asm volatile(
        "mma.sync.aligned.m16n8k16.row.col.f32.f16.f16.f32 "
        "{%0,%1,%2,%3}, {%4,%5,%6,%7}, {%8,%9}, {%0,%1,%2,%3};"
        : "+f"(c[0]), "+f"(c[1]), "+f"(c[2]), "+f"(c[3])
        : "r"(a[0]), "r"(a[1]), "r"(a[2]), "r"(a[3]), "r"(b[0]), "r"(b[1]));
}

// exact R0-numerics distance (ascending-k fp32 FMA chain)
__device__ __forceinline__ float exact_dist(const float* __restrict__ x,
                                            const float* __restrict__ w,
                                            int row, int code) {
    const float* xr = x + (size_t)row * E_DIM;
    const float* wr = w + (size_t)code * E_DIM;
    float acc = 0.f;
    #pragma unroll 8
    for (int k = 0; k < E_DIM; ++k) acc = fmaf(__ldg(xr + k), __ldg(wr + k), acc);
    return fmaf(-2.0f, acc, g_x2[row]) + g_w2[code];
}

// ---------------------------------------------------------------------------
// fused split(w, scale 1024) + w2 : warp per code (w2 numerics == R0)
// ---------------------------------------------------------------------------
__global__ void splitw_w2_kernel(const float* __restrict__ w) {
    int code = (blockIdx.x * blockDim.x + threadIdx.x) >> 5;
    int lane = threadIdx.x & 31;
    if (code >= Q_CODES) return;
    const float* row = w + (size_t)code * E_DIM;
    float v[8];
    float s = 0.f;
    #pragma unroll
    for (int j = 0; j < 8; ++j) {
        v[j] = row[lane + 32 * j];
        s = fmaf(v[j], v[j], s);
    }
    #pragma unroll
    for (int off = 16; off; off >>= 1) s += __shfl_down_sync(0xffffffffu, s, off);
    if (lane == 0) g_w2[code] = s;
    #pragma unroll
    for (int j = 0; j < 8; ++j) {
        float sv = v[j] * 1024.0f;                 // exact
        __half h = __float2half_rn(sv);
        g_wh[(size_t)code * E_DIM + lane + 32 * j] = h;
        g_wl[(size_t)code * E_DIM + lane + 32 * j] = __float2half_rn(sv - __half2float(h));
    }
}

// ---------------------------------------------------------------------------
// vq B tile (hi only): full 128 codes x 256 k per stage
// ---------------------------------------------------------------------------
__device__ __forceinline__ void vq_issue_tile(uint32_t smem_u, int t, int tid) {
    const uint32_t bst = smem_u + ((t & 1) ? BST1_OFF : BST0_OFF);
    const __half* srcH = g_wh + (size_t)(t * BN) * E_DIM;
    #pragma unroll
    for (int it = 0; it < 16; ++it) {
        int i = tid + it * 256;          // 0..4095
        int row = i >> 5, q = i & 31;    // 32 x 16B units per code row
        CP_ASYNC16(bst + (uint32_t)(row * 528 + q * 16),
                   (const void*)(srcH + row * E_DIM + q * 8));
    }
}

// ---------------------------------------------------------------------------
// vq pass: single-pass fp16 mma, full-tile staging, ONE barrier per tile.
// R14: reads fp32 x directly (A convert in-kernel), computes x2 (exact R0
// chain), and resets g_nflag — splitx/x2/reset kernels eliminated.
// ---------------------------------------------------------------------------
__global__ __launch_bounds__(256, 1)
void vq_kernel(const float* __restrict__ x) {
    extern __shared__ __align__(128) char smem[];
    const uint32_t smem_u = smem_u32(smem);
    float* w2s = (float*)(smem + W2S_OFF);
    unsigned long long* sredB = (unsigned long long*)(smem + SREDB_OFF);
    unsigned int*       sredS = (unsigned int*)(smem + SREDS_OFF);

    const int tid  = threadIdx.x;
    const int lane = tid & 31;
    const int wid  = tid >> 5;
    const int wm   = wid >> 2;          // 0..1 -> 64 rows each
    const int wn   = wid & 3;           // 0..3 -> 32 codes each
    const int rowBase = blockIdx.x * BM;

    if (blockIdx.x == 0 && tid == 0) g_nflag = 0;

    vq_issue_tile(smem_u, 0, tid);
    CP_COMMIT();

    {   // resident A: convert fp32 x -> half into smem (row stride 528B)
        const float4* xg = (const float4*)(x + (size_t)rowBase * E_DIM);
        #pragma unroll
        for (int it = 0; it < 32; ++it) {
            int i = tid + it * 256;      // 0..8191
            int r = i >> 6, q = i & 63;  // 64 float4 per row
            float4 v = xg[r * 64 + q];
            __half2 h01 = __halves2half2(__float2half_rn(v.x), __float2half_rn(v.y));
            __half2 h23 = __halves2half2(__float2half_rn(v.z), __float2half_rn(v.w));
            uint2 pk;
            pk.x = *(uint32_t*)&h01;
            pk.y = *(uint32_t*)&h23;
            *(uint2*)(smem + XSH_OFF + r * 528 + q * 8) = pk;
        }
    }
    #pragma unroll
    for (int it = 0; it < 16; ++it) w2s[tid + it * 256] = g_w2[tid + it * 256];
    if (tid < BM) { sredB[tid] = 0xFFFFFFFFFFFFFFFFull; sredS[tid] = 0xFFFFFFFFu; }

    // x2: exact R0 ascending-k fp32 chain, one row per thread (tid<128)
    if (tid < BM) {
        const float4* xr4 = (const float4*)(x + (size_t)(rowBase + tid) * E_DIM);
        float s = 0.f;
        #pragma unroll 8
        for (int q = 0; q < 64; ++q) {
            float4 v = __ldg(xr4 + q);
            s = fmaf(v.x, v.x, s);
            s = fmaf(v.y, v.y, s);
            s = fmaf(v.z, v.z, s);
            s = fmaf(v.w, v.w, s);
        }
        g_x2[rowBase + tid] = s;
    }
    __syncthreads();                     // x2 visible to all threads in CTA

    float x2r[8];
    #pragma unroll
    for (int mf = 0; mf < 4; ++mf)
        #pragma unroll
        for (int h = 0; h < 2; ++h)
            x2r[mf * 2 + h] = g_x2[rowBase + wm * 64 + mf * 16 + h * 8 + (lane >> 2)];

    float bestD[8], secD[8];
    int   bestI[8];
    #pragma unroll
    for (int i = 0; i < 8; ++i) { bestD[i] = INFINITY; secD[i] = INFINITY; bestI[i] = 0; }

    float acc[4][4][4];

    for (int t = 0; t < NTILES; ++t) {
        CP_WAIT0();                      // tile t landed (only group in flight)
        __syncthreads();                 // all threads past tile t-1 reads; data visible
        if (t + 1 < NTILES) { vq_issue_tile(smem_u, t + 1, tid); CP_COMMIT(); }

        const uint32_t bst = smem_u + ((t & 1) ? BST1_OFF : BST0_OFF);

        #pragma unroll
        for (int mf = 0; mf < 4; ++mf)
            #pragma unroll
            for (int nf = 0; nf < 4; ++nf)
                #pragma unroll
                for (int e = 0; e < 4; ++e) acc[mf][nf][e] = 0.f;

        #pragma unroll 4
        for (int kk = 0; kk < 16; ++kk) {
            const int kg = kk * 16;
            uint32_t Ah[4][4], Bh[4][2];
            #pragma unroll
            for (int mf = 0; mf < 4; ++mf) {
                uint32_t off = (uint32_t)((wm * 64 + mf * 16 + (lane & 15)) * 528
                                          + (kg + ((lane >> 4) << 3)) * 2);
                LDMATRIX_X4(Ah[mf][0], Ah[mf][1], Ah[mf][2], Ah[mf][3], smem_u + XSH_OFF + off);
            }
            #pragma unroll
            for (int p = 0; p < 2; ++p) {
                uint32_t n = (uint32_t)(wn * 32 + p * 16 + (lane & 7) + ((lane >> 4) << 3));
                uint32_t off = n * 528 + (uint32_t)((kg + (((lane >> 3) & 1) << 3)) * 2);
                LDMATRIX_X4(Bh[p*2][0], Bh[p*2][1], Bh[p*2+1][0], Bh[p*2+1][1], bst + off);
            }
            #pragma unroll
            for (int mf = 0; mf < 4; ++mf)
                #pragma unroll
                for (int nf = 0; nf < 4; ++nf) mma16816(acc[mf][nf], Ah[mf], Bh[nf]);
        }

        // epilogue tile t (registers + read-only w2s; no barrier needed)
        const int codeBase = t * BN + wn * 32;
        #pragma unroll
        for (int mf = 0; mf < 4; ++mf)
            #pragma unroll
            for (int h = 0; h < 2; ++h) {
                const int slot = mf * 2 + h;
                float x2v = x2r[slot];
                float d0 = bestD[slot], d1 = secD[slot];
                int   i0 = bestI[slot];
                #pragma unroll
                for (int nf = 0; nf < 4; ++nf)
                    #pragma unroll
                    for (int j = 0; j < 2; ++j) {
                        int code  = codeBase + nf * 8 + (lane & 3) * 2 + j;
                        float dot = acc[mf][nf][h * 2 + j] * 0.0009765625f;
                        float dv  = fmaf(-2.0f, dot, x2v) + w2s[code];
                        if (dv < d0)      { d1 = d0; d0 = dv; i0 = code; }
                        else if (dv < d1) { d1 = dv; }
                    }
                bestD[slot] = d0; secD[slot] = d1; bestI[slot] = i0;
            }
    }

    __syncthreads();
    #pragma unroll
    for (int i = 0; i < 8; ++i) {
        int rowLocal = wm * 64 + (i >> 1) * 16 + (i & 1) * 8 + (lane >> 2);
        unsigned long long pack =
            ((unsigned long long)__float_as_uint(bestD[i]) << 32) | (unsigned)bestI[i];
        atomicMin(&sredB[rowLocal], pack);
    }
    __syncthreads();
    #pragma unroll
    for (int i = 0; i < 8; ++i) {
        int rowLocal = wm * 64 + (i >> 1) * 16 + (i & 1) * 8 + (lane >> 2);
        unsigned winIdx = (unsigned)(sredB[rowLocal] & 0xffffffffull);
        float cand = ((unsigned)bestI[i] == winIdx) ? secD[i] : bestD[i];
        atomicMin(&sredS[rowLocal], __float_as_uint(cand));
    }
    __syncthreads();

    if (tid < BM) {
        unsigned long long bp = sredB[tid];
        float bd = __uint_as_float((unsigned)(bp >> 32));
        float sd = __uint_as_float(sredS[tid]);
        int row = rowBase + tid;
        g_bestI[row] = (int)(bp & 0xffffffffull);
        g_bestD[row] = bd;
        g_flag[row]  = (sd - bd <= M_FLAG) ? 1 : 0;
    }
}

// ---------------------------------------------------------------------------
// fused compact + row copy: flagging thread claims slot and writes the
// compacted hi/lo split (identical formula to the proven copyrows path)
// ---------------------------------------------------------------------------
__global__ void compactcopy_kernel(const float* __restrict__ x) {
    int r = blockIdx.x * blockDim.x + threadIdx.x;
    if (r >= ROWS_TOT) return;
    if (!g_flag[r]) return;
    int p = atomicAdd(&g_nflag, 1);
    g_flagrows[p] = r;
    g_red[r] = 0xFFFFFFFFFFFFFFFFull;

    const float4* src = (const float4*)(x + (size_t)r * E_DIM);
    __half2* dh = (__half2*)(g_xh2 + (size_t)p * E_DIM);
    __half2* dl = (__half2*)(g_xl2 + (size_t)p * E_DIM);
    #pragma unroll 4
    for (int q = 0; q < 64; ++q) {
        float4 v4 = __ldg(src + q);
        float f[4] = {v4.x, v4.y, v4.z, v4.w};
        __half h[4], l[4];
        #pragma unroll
        for (int j = 0; j < 4; ++j) {
            h[j] = __float2half_rn(f[j]);
            l[j] = __float2half_rn(f[j] - __half2float(h[j]));
        }
        dh[q * 2]     = __halves2half2(h[0], h[1]);
        dh[q * 2 + 1] = __halves2half2(h[2], h[3]);
        dl[q * 2]     = __halves2half2(l[0], l[1]);
        dl[q * 2 + 1] = __halves2half2(l[2], l[3]);
    }
}

// ---------------------------------------------------------------------------
// refine B chunk (hi + lo)  [unchanged, proven]
// ---------------------------------------------------------------------------
__device__ __forceinline__ void rf_issue_chunk(uint32_t smem_u, int quarter, int s, int tid) {
    const int t = s >> 2, c = s & 3;
    const int codeBase = quarter * 1024 + t * BN;
    const uint32_t bst = smem_u + ((s & 1) ? RB1_OFF : RB0_OFF);
    const __half* srcH = g_wh + (size_t)codeBase * E_DIM + c * 64;
    const __half* srcL = g_wl + (size_t)codeBase * E_DIM + c * 64;
    #pragma unroll
    for (int it = 0; it < 4; ++it) {
        int i = tid + it * 256;
        int row = i >> 3, q = i & 7;
        uint32_t dst = bst + (uint32_t)(row * BS_ROW_BYTES + q * 16);
        CP_ASYNC16(dst, (const void*)(srcH + row * E_DIM + q * 8));
        CP_ASYNC16(dst + B_TYPE_BYTES, (const void*)(srcL + row * E_DIM + q * 8));
    }
}

// ---------------------------------------------------------------------------
// refine: flagged rows, 3-pass fp16 mma; candidates (dv <= bestD+M) -> exact
// ---------------------------------------------------------------------------
__global__ __launch_bounds__(256, 1)
void refine_kernel(const float* __restrict__ x, const float* __restrict__ w) {
    extern __shared__ __align__(128) char smem[];
    const uint32_t smem_u = smem_u32(smem);
    float* w2q  = (float*)(smem + RW2_OFF);
    int*   srow = (int*)(smem + RROW_OFF);

    const int tid  = threadIdx.x;
    const int lane = tid & 31;
    const int wid  = tid >> 5;
    const int wm   = wid >> 2;          // 0..1 -> 16 rows each
    const int wn   = wid & 3;

    const int nflag  = g_nflag;
    const int nItems = ((nflag + 31) >> 5) * 4;

    for (int item = blockIdx.x; item < nItems; item += gridDim.x) {
        const int grp = item >> 2, quarter = item & 3;
        __syncthreads();                 // smem reuse across items

        rf_issue_chunk(smem_u, quarter, 0, tid);
        CP_COMMIT();

        #pragma unroll
        for (int it = 0; it < 4; ++it) {
            int i = tid + it * 256;      // 0..1023
            int r = i >> 5, q = i & 31;
            int p = grp * 32 + r; if (p >= nflag) p = nflag - 1;
            *(uint4*)(smem + RXH_OFF + r * 528 + q * 16) =
                ((const uint4*)(g_xh2 + (size_t)p * E_DIM))[q];
            *(uint4*)(smem + RXL_OFF + r * 528 + q * 16) =
                ((const uint4*)(g_xl2 + (size_t)p * E_DIM))[q];
        }
        #pragma unroll
        for (int it = 0; it < 4; ++it)
            w2q[tid + it * 256] = g_w2[quarter * 1024 + tid + it * 256];
        if (tid < 32) {
            int p = grp * 32 + tid; if (p >= nflag) p = nflag - 1;
            srow[tid] = g_flagrows[p];
        }
        __syncthreads();

        int   rid[2]; float x2v[2], thr[2];
        #pragma unroll
        for (int h = 0; h < 2; ++h) {
            int rl = wm * 16 + h * 8 + (lane >> 2);
            rid[h] = srow[rl];
            x2v[h] = g_x2[rid[h]];
            thr[h] = g_bestD[rid[h]] + M_COLL;
        }

        for (int t = 0; t < 8; ++t) {
            float acc[4][4];
            #pragma unroll
            for (int nf = 0; nf < 4; ++nf)
                #pragma unroll
                for (int e = 0; e < 4; ++e) acc[nf][e] = 0.f;

            for (int c = 0; c < 4; ++c) {
                const int s = t * 4 + c;
                if (s + 1 < 32) { rf_issue_chunk(smem_u, quarter, s + 1, tid); CP_COMMIT(); CP_WAIT1(); }
                else            { CP_WAIT0(); }
                __syncthreads();

                const uint32_t bst = smem_u + ((s & 1) ? RB1_OFF : RB0_OFF);

                #pragma unroll
                for (int kk = 0; kk < 4; ++kk) {
                    const int kg = c * 64 + kk * 16;
                    const int kl = kk * 16;
                    uint32_t Ah[4], Al[4], Bh[4][2], Bl[4][2];
                    {
                        uint32_t off = (uint32_t)((wm * 16 + (lane & 15)) * 528
                                                  + (kg + ((lane >> 4) << 3)) * 2);
                        LDMATRIX_X4(Ah[0], Ah[1], Ah[2], Ah[3], smem_u + RXH_OFF + off);
                        LDMATRIX_X4(Al[0], Al[1], Al[2], Al[3], smem_u + RXL_OFF + off);
                    }
                    #pragma unroll
                    for (int p = 0; p < 2; ++p) {
                        uint32_t n = (uint32_t)(wn * 32 + p * 16 + (lane & 7) + ((lane >> 4) << 3));
                        uint32_t off = n * BS_ROW_BYTES + (uint32_t)((kl + (((lane >> 3) & 1) << 3)) * 2);
                        LDMATRIX_X4(Bh[p*2][0], Bh[p*2][1], Bh[p*2+1][0], Bh[p*2+1][1], bst + off);
                        LDMATRIX_X4(Bl[p*2][0], Bl[p*2][1], Bl[p*2+1][0], Bl[p*2+1][1],
                                    bst + B_TYPE_BYTES + off);
                    }
                    #pragma unroll
                    for (int nf = 0; nf < 4; ++nf) mma16816(acc[nf], Ah, Bh[nf]);
                    #pragma unroll
                    for (int nf = 0; nf < 4; ++nf) mma16816(acc[nf], Al, Bh[nf]);
                    #pragma unroll
                    for (int nf = 0; nf < 4; ++nf) mma16816(acc[nf], Ah, Bl[nf]);
                }
                __syncthreads();
            }

            const int codeBase = quarter * 1024 + t * BN + wn * 32;
            #pragma unroll
            for (int h = 0; h < 2; ++h)
                #pragma unroll
                for (int nf = 0; nf < 4; ++nf)
                    #pragma unroll
                    for (int j = 0; j < 2; ++j) {
                        int code  = codeBase + nf * 8 + (lane & 3) * 2 + j;
                        float dot = acc[nf][h * 2 + j] * 0.0009765625f;
                        float dv  = fmaf(-2.0f, dot, x2v[h]) + w2q[t * BN + wn * 32 + nf * 8 + (lane & 3) * 2 + j];
                        if (dv <= thr[h]) {
                            float de = exact_dist(x, w, rid[h], code);
                            unsigned long long pack =
                                ((unsigned long long)__float_as_uint(de) << 32) | (unsigned)code;
                            atomicMin(&g_red[rid[h]], pack);
                        }
                    }
        }
    }
}

// ---------------------------------------------------------------------------
// gather: 4 rows per 256-thread block
// ---------------------------------------------------------------------------
__global__ void gather_kernel(const float* __restrict__ w, float* __restrict__ out,
                              float* __restrict__ out_idx_f) {
    const int t   = threadIdx.x;
    const int row = blockIdx.x * 4 + (t >> 6);
    const int q   = t & 63;
    int idx = g_flag[row] ? (int)(g_red[row] & 0xffffffffull) : g_bestI[row];
    ((float4*)(out + (size_t)row * E_DIM))[q] =
        ((const float4*)(w + (size_t)idx * E_DIM))[q];
    if (q == 0) out_idx_f[row] = (float)idx;
}

// ---------------------------------------------------------------------------
extern "C" void kernel_launch(void* const* d_in, const int* in_sizes, int n_in,
                              void* d_out, int out_size) {
    const float* x = (const float*)d_in[0];
    const float* w = (const float*)d_in[1];
    int rows = in_sizes[0] / E_DIM;        // 32768

    float* out     = (float*)d_out;
    float* out_idx = out + (size_t)rows * E_DIM;

    cudaFuncSetAttribute(vq_kernel,
                         cudaFuncAttributeMaxDynamicSharedMemorySize, VQ_SMEM);
    cudaFuncSetAttribute(refine_kernel,
                         cudaFuncAttributeMaxDynamicSharedMemorySize, RF_SMEM);

    splitw_w2_kernel<<<Q_CODES / 8, 256>>>(w);                // 1
    vq_kernel<<<rows / BM, 256, VQ_SMEM>>>(x);                // 2
    compactcopy_kernel<<<(ROWS_TOT + 255) / 256, 256>>>(x);   // 3
    refine_kernel<<<296, 256, RF_SMEM>>>(x, w);               // 4  <- ncu target
    gather_kernel<<<rows / 4, 256>>>(w, out, out_idx);        // 5
}